// round 3
// baseline (speedup 1.0000x reference)
#include <cuda_runtime.h>
#include <cuda_bf16.h>

// out[b, d] = x[b, d] * clamp(diagonal[d], -0.95, 0.95)
// BATCH = 16384, LATENT_DIM = 8192, fp32. 1 GiB streamed, HBM-bound.
//
// R3: persistent single-wave launch. Each thread owns 4 fixed columns:
//     diag loaded + clamped ONCE into registers, then a tight row loop of
//     4x LDG.128 (streaming) + 4x STG.128 (streaming). No wave transitions,
//     no per-iteration diag traffic, no modulo.

#define LATENT_DIM 8192
#define BATCH 16384
#define COLS4 (LATENT_DIM / 4)        // 2048 float4 per row
#define TPB 256
#define UNROLL 4
#define CHUNK (TPB * UNROLL)          // 1024 float4 per block
#define BLOCKS_X (COLS4 / CHUNK)      // 2 column-blocks per row
#define ROWS_ACTIVE 592               // 2 * 592 = 1184 CTAs = 148 SMs * 8

__global__ __launch_bounds__(TPB)
void diag_linear_kernel(const float4* __restrict__ x,
                        const float4* __restrict__ diag,
                        float4* __restrict__ out) {
    const int base_col = blockIdx.x * CHUNK + threadIdx.x;   // warp-coalesced

    // Load + clamp diagonal ONCE; lives in registers for the whole kernel.
    float4 d[UNROLL];
#pragma unroll
    for (int k = 0; k < UNROLL; k++) {
        float4 s = __ldg(&diag[base_col + k * TPB]);
        s.x = fminf(fmaxf(s.x, -0.95f), 0.95f);
        s.y = fminf(fmaxf(s.y, -0.95f), 0.95f);
        s.z = fminf(fmaxf(s.z, -0.95f), 0.95f);
        s.w = fminf(fmaxf(s.w, -0.95f), 0.95f);
        d[k] = s;
    }

    // Persistent row loop: stride = ROWS_ACTIVE rows.
    for (long long row = blockIdx.y; row < BATCH; row += ROWS_ACTIVE) {
        const long long off = row * COLS4 + base_col;

        float4 v[UNROLL];
#pragma unroll
        for (int k = 0; k < UNROLL; k++)
            v[k] = __ldcs(&x[off + k * TPB]);     // read-once: evict-first

#pragma unroll
        for (int k = 0; k < UNROLL; k++) {
            v[k].x *= d[k].x;
            v[k].y *= d[k].y;
            v[k].z *= d[k].z;
            v[k].w *= d[k].w;
        }

#pragma unroll
        for (int k = 0; k < UNROLL; k++)
            __stcs(&out[off + k * TPB], v[k]);    // streaming store
    }
}

extern "C" void kernel_launch(void* const* d_in, const int* in_sizes, int n_in,
                              void* d_out, int out_size) {
    const float4* x    = (const float4*)d_in[0];
    const float4* diag = (const float4*)d_in[1];
    float4* out        = (float4*)d_out;

    dim3 grid(BLOCKS_X, ROWS_ACTIVE, 1);
    diag_linear_kernel<<<grid, TPB>>>(x, diag, out);
}

// round 4
// speedup vs baseline: 1.0461x; 1.0461x over previous
#include <cuda_runtime.h>
#include <cuda_bf16.h>

// out[b, d] = x[b, d] * clamp(diagonal[d], -0.95, 0.95)
// BATCH = 16384, LATENT_DIM = 8192, fp32. 1 GiB streamed, HBM-bound.
//
// R4: back to the R2 regime (max occupancy + MLP=4). One CTA = one row:
//     TPB=512, UNROLL=4 -> 512*4 float4 = 2048 float4 = 8192 floats.
//     1D grid of 16384 CTAs. __ldlu (last-use) reads, __stcs writes.

#define LATENT_DIM 8192
#define BATCH 16384
#define COLS4 (LATENT_DIM / 4)        // 2048 float4 per row
#define TPB 512
#define UNROLL 4                      // TPB * UNROLL == COLS4

__global__ __launch_bounds__(TPB)
void diag_linear_kernel(const float4* __restrict__ x,
                        const float4* __restrict__ diag,
                        float4* __restrict__ out) {
    const int col = threadIdx.x;                       // 0 .. 511
    const long long off = (long long)blockIdx.x * COLS4 + col;

    // Front-batched independent loads: 4x LDG.128 (x, last-use) + 4x diag (hot).
    float4 v[UNROLL];
    float4 d[UNROLL];
#pragma unroll
    for (int k = 0; k < UNROLL; k++) {
        v[k] = __ldlu(&x[off + k * TPB]);   // read exactly once -> evict ASAP
        d[k] = __ldg(&diag[col + k * TPB]); // 32 KiB, L1/L2 resident
    }

#pragma unroll
    for (int k = 0; k < UNROLL; k++) {
        float4 s = d[k];
        s.x = fminf(fmaxf(s.x, -0.95f), 0.95f);
        s.y = fminf(fmaxf(s.y, -0.95f), 0.95f);
        s.z = fminf(fmaxf(s.z, -0.95f), 0.95f);
        s.w = fminf(fmaxf(s.w, -0.95f), 0.95f);
        v[k].x *= s.x;
        v[k].y *= s.y;
        v[k].z *= s.z;
        v[k].w *= s.w;
    }

#pragma unroll
    for (int k = 0; k < UNROLL; k++)
        __stcs(&out[off + k * TPB], v[k]);  // streaming store

}

extern "C" void kernel_launch(void* const* d_in, const int* in_sizes, int n_in,
                              void* d_out, int out_size) {
    const float4* x    = (const float4*)d_in[0];
    const float4* diag = (const float4*)d_in[1];
    float4* out        = (float4*)d_out;

    diag_linear_kernel<<<BATCH, TPB>>>(x, diag, out);
}